// round 17
// baseline (speedup 1.0000x reference)
#include <cuda_runtime.h>
#include <cuda_fp16.h>
#include <math.h>

#define N_NODES 100000
#define N_EDGES 1600000
#define IN_F 128
#define OUT_F 32
#define NEG_SLOPE 0.2f

#define ROWS_PB 128
#define K1_BLOCKS ((N_NODES + ROWS_PB - 1) / ROWS_PB)   // 782

#define SCAN_CHUNK 1024
#define SCAN_BLOCKS ((N_NODES + SCAN_CHUNK - 1) / SCAN_CHUNK)  // 98

// Scratch (device globals: no allocation allowed; zero-init at load)
__device__ __half g_zh[(size_t)N_NODES * OUT_F];   // z in fp16 (6.4 MB)
__device__ float g_el[N_NODES];
__device__ float g_er[N_NODES];
__device__ int   g_cnt[N_NODES];      // hist counts; ZERO ON ENTRY (reset by k_aggregate)
__device__ int   g_off[N_NODES];      // chunk-local exclusive offsets (stable)
__device__ int   g_bsum[SCAN_BLOCKS]; // per-chunk totals
__device__ int   g_rank[N_EDGES];     // per-edge rank within its dst node
__device__ int   g_srce[N_EDGES];     // src ids sorted by dst

// ---------------------------------------------------------------------------
__device__ __forceinline__ void cp_async16(unsigned smem_addr, const void* gptr)
{
    asm volatile("cp.async.cg.shared.global [%0], [%1], 16;"
                 :: "r"(smem_addr), "l"(gptr) : "memory");
}

// helper: 98-entry exclusive prefix of g_bsum into smem pref[]
__device__ __forceinline__ void chunk_prefix(int* pref, int tid)
{
    int own = 0;
    if (tid < 128) {
        own = (tid < SCAN_BLOCKS) ? g_bsum[tid] : 0;
        pref[tid] = own;
    }
    __syncthreads();
    #pragma unroll
    for (int o = 1; o < 128; o <<= 1) {
        int v = 0;
        if (tid < 128 && tid >= o) v = pref[tid - o];
        __syncthreads();
        if (tid < 128) pref[tid] += v;
        __syncthreads();
    }
    if (tid < 128) pref[tid] -= own;     // inclusive -> exclusive
    __syncthreads();
}

// ---------------------------------------------------------------------------
// K1: z = h @ W^T (fp16 store) + el/er + FUSED dst-histogram/rank.
// cp.async 2-stage pipeline: 4 stages x 32 rows; h streamed into smem with
// no register dependence -> bytes-in-flight bounded by smem, not regfile.
// Hist work issued between prologue and compute loop to hide in stream stalls.
// Thread tile: 4 rows (one per stage) x 4 cols. Swizzle (k4+r)&31 keeps the
// 4 per-warp row reads bank-disjoint.
// ---------------------------------------------------------------------------
__global__ __launch_bounds__(256) void k_gemm(
    const float* __restrict__ h, const float* __restrict__ W,
    const float* __restrict__ a, const int* __restrict__ dst)
{
    __shared__ float4 hs[2][32][32];        // 32 KB (2 stages x 32 rows x 128f)
    __shared__ float  Wt[IN_F][OUT_F];      // 16 KB  -> exactly 48 KB static

    const int tid  = threadIdx.x;
    const int row0 = blockIdx.x * ROWS_PB;
    const float4* h4 = (const float4*)h;

    unsigned hs_base;
    {
        unsigned long long t;
        asm("cvta.to.shared.u64 %0, %1;" : "=l"(t) : "l"(&hs[0][0][0]));
        hs_base = (unsigned)t;
    }

    // stage issuer: stage s (rows row0+32s..+31) into buffer buf
    auto stage_issue = [&](int s, int buf) {
        #pragma unroll
        for (int i = 0; i < 4; i++) {
            int idx = i * 256 + tid;        // 0..1023 over [32 rows][32 f4]
            int r = idx >> 5;
            int c = idx & 31;
            int gr = row0 + s * 32 + r;
            if (gr > N_NODES - 1) gr = N_NODES - 1;
            unsigned daddr = hs_base +
                ((unsigned)(buf * 1024 + r * 32 + ((c + r) & 31)) << 4);
            cp_async16(daddr, h4 + (size_t)gr * 32 + c);
        }
    };

    // prologue: get the stream going immediately
    stage_issue(0, 0);
    asm volatile("cp.async.commit_group;" ::: "memory");
    stage_issue(1, 1);
    asm volatile("cp.async.commit_group;" ::: "memory");

    // stage W transposed (plain LDG/STS, overlaps with cp.async stream)
    for (int i = tid; i < IN_F * OUT_F; i += 256) {
        int j = i >> 7;
        int k = i & 127;
        Wt[k][j] = W[i];
    }

    // FUSED hist + rank (g_cnt zero on entry by invariant)
    {
        const int n4 = N_EDGES / 4;
        for (int i = blockIdx.x * 256 + tid; i < n4; i += K1_BLOCKS * 256) {
            int4 dv = ((const int4*)dst)[i];
            int4 rv;
            rv.x = atomicAdd(&g_cnt[dv.x], 1);
            rv.y = atomicAdd(&g_cnt[dv.y], 1);
            rv.z = atomicAdd(&g_cnt[dv.z], 1);
            rv.w = atomicAdd(&g_cnt[dv.w], 1);
            ((int4*)g_rank)[i] = rv;
        }
    }

    const int col0 = (tid & 7) * 4;
    const int rs   = tid >> 3;              // row within stage (0..31)

    float4 acc[4];
    #pragma unroll
    for (int i = 0; i < 4; i++) acc[i] = make_float4(0.f, 0.f, 0.f, 0.f);

    #pragma unroll
    for (int s = 0; s < 4; s++) {
        if (s == 3) asm volatile("cp.async.wait_group 0;" ::: "memory");
        else        asm volatile("cp.async.wait_group 1;" ::: "memory");
        __syncthreads();

        const int buf = s & 1;
        #pragma unroll 8
        for (int k4 = 0; k4 < IN_F / 4; k4++) {
            float4 wv0 = *(const float4*)&Wt[k4 * 4 + 0][col0];
            float4 wv1 = *(const float4*)&Wt[k4 * 4 + 1][col0];
            float4 wv2 = *(const float4*)&Wt[k4 * 4 + 2][col0];
            float4 wv3 = *(const float4*)&Wt[k4 * 4 + 3][col0];
            float4 hv  = hs[buf][rs][(k4 + rs) & 31];
            acc[s].x = fmaf(hv.x, wv0.x, acc[s].x);
            acc[s].y = fmaf(hv.x, wv0.y, acc[s].y);
            acc[s].z = fmaf(hv.x, wv0.z, acc[s].z);
            acc[s].w = fmaf(hv.x, wv0.w, acc[s].w);
            acc[s].x = fmaf(hv.y, wv1.x, acc[s].x);
            acc[s].y = fmaf(hv.y, wv1.y, acc[s].y);
            acc[s].z = fmaf(hv.y, wv1.z, acc[s].z);
            acc[s].w = fmaf(hv.y, wv1.w, acc[s].w);
            acc[s].x = fmaf(hv.z, wv2.x, acc[s].x);
            acc[s].y = fmaf(hv.z, wv2.y, acc[s].y);
            acc[s].z = fmaf(hv.z, wv2.z, acc[s].z);
            acc[s].w = fmaf(hv.z, wv2.w, acc[s].w);
            acc[s].x = fmaf(hv.w, wv3.x, acc[s].x);
            acc[s].y = fmaf(hv.w, wv3.y, acc[s].y);
            acc[s].z = fmaf(hv.w, wv3.z, acc[s].z);
            acc[s].w = fmaf(hv.w, wv3.w, acc[s].w);
        }
        __syncthreads();                     // everyone done reading buf
        if (s < 2) {
            stage_issue(s + 2, buf);
            asm volatile("cp.async.commit_group;" ::: "memory");
        }
    }

    // epilogue: z (fp16) + el/er. Thread's row for "stage" i: row0+32i+rs.
    const float4 al4 = *(const float4*)&a[col0];
    const float4 ar4 = *(const float4*)&a[OUT_F + col0];

    #pragma unroll
    for (int i = 0; i < 4; i++) {
        int r = row0 + 32 * i + rs;
        bool ok = (r < N_NODES);
        if (ok) {
            __half2 p0 = __floats2half2_rn(acc[i].x, acc[i].y);
            __half2 p1 = __floats2half2_rn(acc[i].z, acc[i].w);
            uint2 pk;
            pk.x = *(unsigned*)&p0;
            pk.y = *(unsigned*)&p1;
            ((uint2*)g_zh)[(size_t)r * (OUT_F / 4) + (col0 >> 2)] = pk;
        }

        float pel = acc[i].x * al4.x + acc[i].y * al4.y
                  + acc[i].z * al4.z + acc[i].w * al4.w;
        float per = acc[i].x * ar4.x + acc[i].y * ar4.y
                  + acc[i].z * ar4.z + acc[i].w * ar4.w;
        #pragma unroll
        for (int o = 4; o > 0; o >>= 1) {
            pel += __shfl_xor_sync(0xffffffffu, pel, o);
            per += __shfl_xor_sync(0xffffffffu, per, o);
        }
        if (ok && (tid & 7) == 0) {
            g_el[r] = pel;
            g_er[r] = per;
        }
    }
}

// ---------------------------------------------------------------------------
// B: per-chunk exclusive scan of g_cnt -> g_off (chunk-local), total -> g_bsum
// ---------------------------------------------------------------------------
__global__ __launch_bounds__(SCAN_CHUNK) void k_scan_local()
{
    __shared__ int wsum[32];
    int t = threadIdx.x;
    int i = blockIdx.x * SCAN_CHUNK + t;
    int c = (i < N_NODES) ? g_cnt[i] : 0;
    int lane = t & 31, wid = t >> 5;

    int incl = c;
    #pragma unroll
    for (int o = 1; o < 32; o <<= 1) {
        int v = __shfl_up_sync(0xffffffffu, incl, o);
        if (lane >= o) incl += v;
    }
    if (lane == 31) wsum[wid] = incl;
    __syncthreads();
    if (wid == 0) {
        int w = wsum[lane];
        int wincl = w;
        #pragma unroll
        for (int o = 1; o < 32; o <<= 1) {
            int v = __shfl_up_sync(0xffffffffu, wincl, o);
            if (lane >= o) wincl += v;
        }
        wsum[lane] = wincl - w;
        if (lane == 31) g_bsum[blockIdx.x] = wincl;
    }
    __syncthreads();
    if (i < N_NODES) g_off[i] = wsum[wid] + incl - c;   // chunk-local exclusive
}

// ---------------------------------------------------------------------------
// C: ATOMIC-FREE scatter: pos = off[d] + pref + rank[e].
// ---------------------------------------------------------------------------
__global__ __launch_bounds__(256) void k_scatter(
    const int* __restrict__ src, const int* __restrict__ dst)
{
    __shared__ int pref[128];
    const int tid = threadIdx.x;
    chunk_prefix(pref, tid);

    int idx = blockIdx.x * 256 + tid;
    if (idx >= N_EDGES / 4) return;
    int4 sv = ((const int4*)src)[idx];
    int4 dv = ((const int4*)dst)[idx];
    int4 rv = ((const int4*)g_rank)[idx];

    g_srce[g_off[dv.x] + pref[dv.x >> 10] + rv.x] = sv.x;
    g_srce[g_off[dv.y] + pref[dv.y >> 10] + rv.y] = sv.y;
    g_srce[g_off[dv.z] + pref[dv.z >> 10] + rv.z] = sv.z;
    g_srce[g_off[dv.w] + pref[dv.w >> 10] + rv.w] = sv.w;
}

// ---------------------------------------------------------------------------
// D: one warp per node (R16 structure) + resets g_cnt for next replay.
// ---------------------------------------------------------------------------
__global__ __launch_bounds__(256) void k_aggregate(float* __restrict__ out)
{
    __shared__ int pref[128];
    const int tid = threadIdx.x;
    chunk_prefix(pref, tid);

    int node = blockIdx.x * 8 + (tid >> 5);   // 12500*8 == N_NODES, no tail
    int lane = tid & 31;
    int seg  = lane & 7;
    int grp  = lane >> 3;

    int cnt   = g_cnt[node];
    int start = g_off[node] + pref[node >> 10];
    float er_n = g_er[node];

    if (lane == 0) g_cnt[node] = 0;     // zero-on-entry invariant for k_gemm

    float4 acc = make_float4(0.f, 0.f, 0.f, 0.f);
    float exsum = 0.0f;

    for (int b = 0; b < cnt; b += 32) {
        int nb = cnt - b;                      // warp-uniform
        if (nb > 32) nb = 32;

        bool v = (lane < nb);
        int sn = 0;
        float ex = 0.0f;
        if (v) {
            sn = g_srce[start + b + lane];
            float e = g_el[sn] + er_n;
            e = (e > 0.0f) ? e : NEG_SLOPE * e;
            ex = __expf(e);
        }
        exsum += ex;

        int iters = (nb + 3) >> 2;             // warp-uniform
        #pragma unroll 4
        for (int it = 0; it < iters; it++) {
            int sl = it * 4 + grp;
            int   snb = __shfl_sync(0xffffffffu, sn, sl);
            float exb = __shfl_sync(0xffffffffu, ex, sl);  // 0 for invalid
            uint2 zz = ((const uint2*)g_zh)[(size_t)snb * (OUT_F / 4) + seg];
            float2 f01 = __half22float2(*(__half2*)&zz.x);
            float2 f23 = __half22float2(*(__half2*)&zz.y);
            acc.x = fmaf(exb, f01.x, acc.x);
            acc.y = fmaf(exb, f01.y, acc.y);
            acc.z = fmaf(exb, f23.x, acc.z);
            acc.w = fmaf(exb, f23.y, acc.w);
        }
    }

    #pragma unroll
    for (int o = 1; o < 32; o <<= 1)
        exsum += __shfl_xor_sync(0xffffffffu, exsum, o);
    #pragma unroll
    for (int o = 8; o <= 16; o <<= 1) {
        acc.x += __shfl_xor_sync(0xffffffffu, acc.x, o);
        acc.y += __shfl_xor_sync(0xffffffffu, acc.y, o);
        acc.z += __shfl_xor_sync(0xffffffffu, acc.z, o);
        acc.w += __shfl_xor_sync(0xffffffffu, acc.w, o);
    }

    float inv = 1.0f / fmaxf(exsum, 1e-16f);
    if (grp == 0) {
        float4 r = make_float4(acc.x * inv, acc.y * inv, acc.z * inv, acc.w * inv);
        ((float4*)(out + (size_t)node * OUT_F))[seg] = r;
    }
}

// ---------------------------------------------------------------------------
extern "C" void kernel_launch(void* const* d_in, const int* in_sizes, int n_in,
                              void* d_out, int out_size)
{
    const float* h   = (const float*)d_in[0];
    const float* W   = (const float*)d_in[1];
    const float* a   = (const float*)d_in[2];
    const int*   src = (const int*)d_in[3];
    const int*   dst = (const int*)d_in[4];
    float* out = (float*)d_out;

    (void)in_sizes; (void)n_in; (void)out_size;

    k_gemm<<<K1_BLOCKS, 256>>>(h, W, a, dst);                  // 782 (gemm+hist)
    k_scan_local<<<SCAN_BLOCKS, SCAN_CHUNK>>>();               // 98
    k_scatter<<<(N_EDGES / 4 + 255) / 256, 256>>>(src, dst);   // 1563
    k_aggregate<<<(N_NODES + 7) / 8, 256>>>(out);              // 12500
}